// round 6
// baseline (speedup 1.0000x reference)
#include <cuda_runtime.h>
#include <cuda_bf16.h>
#include <cstdint>

#define B_   512
#define NC   225
#define CK   256
#define MH   225
#define VD   256
#define OUTC 512

// p^T scratch, bf16 hi/lo packed pairs: [B][256 m][128 words(=256 n)]
__device__ uint32_t g_pt_hi[(size_t)B_ * 256 * 128];
__device__ uint32_t g_pt_lo[(size_t)B_ * 256 * 128];

// ---------------- helpers ----------------
__device__ __forceinline__ uint32_t smem_u32(const void* p) {
    uint32_t a;
    asm("{ .reg .u64 t; cvta.to.shared.u64 t, %1; cvt.u32.u64 %0, t; }" : "=r"(a) : "l"(p));
    return a;
}
__device__ __forceinline__ uint32_t pack_hi2(float a, float b, uint32_t& lo) {
    __nv_bfloat16 ha = __float2bfloat16(a), hb = __float2bfloat16(b);
    __nv_bfloat16 la = __float2bfloat16(a - __bfloat162float(ha));
    __nv_bfloat16 lb = __float2bfloat16(b - __bfloat162float(hb));
    lo = (uint32_t)__bfloat16_as_ushort(la) | ((uint32_t)__bfloat16_as_ushort(lb) << 16);
    return (uint32_t)__bfloat16_as_ushort(ha) | ((uint32_t)__bfloat16_as_ushort(hb) << 16);
}
__device__ __forceinline__ void ldm4(uint32_t* r, uint32_t addr) {
    asm volatile("ldmatrix.sync.aligned.m8n8.x4.shared.b16 {%0,%1,%2,%3}, [%4];"
                 : "=r"(r[0]), "=r"(r[1]), "=r"(r[2]), "=r"(r[3]) : "r"(addr));
}
__device__ __forceinline__ void mma16816(float* d, const uint32_t* a, uint32_t b0, uint32_t b1) {
    asm volatile("mma.sync.aligned.m16n8k16.row.col.f32.bf16.bf16.f32 "
                 "{%0,%1,%2,%3}, {%4,%5,%6,%7}, {%8,%9}, {%0,%1,%2,%3};"
                 : "+f"(d[0]), "+f"(d[1]), "+f"(d[2]), "+f"(d[3])
                 : "r"(a[0]), "r"(a[1]), "r"(a[2]), "r"(a[3]), "r"(b0), "r"(b1));
}
__device__ __forceinline__ int iabs(int x) { return x < 0 ? -x : x; }

// smem per buffer (K=16 chunk, pitch 48B):
//   AH 64x48=3072 | AL 3072 | BH 256x48=12288 | BL 12288  => 30720
#define AL_O   3072
#define BH_O   6144
#define BL_O   18432
#define BUFSZ  30720
#define PW_O   61440             // 36 floats
#define RMX_O  61584             // 2*64 floats
#define RS_O   62096             // 2*64 floats
#define SM_G1  62608
#define SM_G2  61440

// =============================== GEMM1 =====================================
// Tile 64m x 256n. 256 thr, 8 warps: mw = w&3 (m strip 16), nh = w>>2 (n half)
__global__ __launch_bounds__(256, 2)
void k_g1(const float* __restrict__ q_in, const float* __restrict__ m_in,
          float* __restrict__ p_out)
{
    extern __shared__ char sm[];
    const uint32_t su = smem_u32(sm);
    const int tid = threadIdx.x, lane = tid & 31, w = tid >> 5;
    const int mw = w & 3, nh = w >> 2;
    const int b = blockIdx.y, m0 = blockIdx.x * 64;

    float* PWS = (float*)(sm + PW_O);
    float* RMX = (float*)(sm + RMX_O);
    float* RS  = (float*)(sm + RS_O);
    if (tid < 36) {
        float v = 0.0625f;
        for (int i = 0; i < tid; i++) v *= 0.92f;
        PWS[tid] = v;
    }

    const float* Aq = q_in + (size_t)b * CK * MH;   // [c][m]
    const float* Bm = m_in + (size_t)b * NC * CK;   // [n][c]

    float acc[16][4];
    #pragma unroll
    for (int i = 0; i < 16; i++) { acc[i][0] = acc[i][1] = acc[i][2] = acc[i][3] = 0.f; }

    const int g = lane >> 3, rr = lane & 7;
    const uint32_t a_base = su + (uint32_t)((mw * 16 + (g & 1) * 8 + rr) * 48 + (g >> 1) * 16);
    const uint32_t b_base = su + BH_O + (uint32_t)((nh * 128 + (g & 1) * 8 + rr) * 48 + (g >> 1) * 16);

    const int amm = tid & 63, acg = (tid >> 6) * 4;   // A: row m, 4 c's
    const int agm = m0 + amm;
    const int bnn = tid;                              // B: one n row, 16 c's
    float fa[4], fb[16];

    auto LOAD = [&](int ch) {
        const int c0 = ch * 16;
        #pragma unroll
        for (int t = 0; t < 4; t++)
            fa[t] = (agm < MH) ? Aq[(size_t)(c0 + acg + t) * MH + agm] : 0.0f;
        if (bnn < NC) {
            const float* br = Bm + (size_t)bnn * CK + c0;
            #pragma unroll
            for (int t = 0; t < 4; t++) *(float4*)(fb + 4 * t) = *(const float4*)(br + 4 * t);
        } else {
            #pragma unroll
            for (int t = 0; t < 16; t++) fb[t] = 0.0f;
        }
    };
    auto CVSTS = [&](int bo) {
        uint2 hv, lv;
        hv.x = pack_hi2(fa[0], fa[1], lv.x); hv.y = pack_hi2(fa[2], fa[3], lv.y);
        *(uint2*)(sm + bo + amm * 48 + acg * 2) = hv;
        *(uint2*)(sm + bo + AL_O + amm * 48 + acg * 2) = lv;
        uint4 h1, l1, h2, l2v;
        h1.x = pack_hi2(fb[0], fb[1], l1.x);  h1.y = pack_hi2(fb[2], fb[3], l1.y);
        h1.z = pack_hi2(fb[4], fb[5], l1.z);  h1.w = pack_hi2(fb[6], fb[7], l1.w);
        h2.x = pack_hi2(fb[8], fb[9], l2v.x); h2.y = pack_hi2(fb[10], fb[11], l2v.y);
        h2.z = pack_hi2(fb[12], fb[13], l2v.z); h2.w = pack_hi2(fb[14], fb[15], l2v.w);
        *(uint4*)(sm + bo + BH_O + bnn * 48) = h1;
        *(uint4*)(sm + bo + BH_O + bnn * 48 + 16) = h2;
        *(uint4*)(sm + bo + BL_O + bnn * 48) = l1;
        *(uint4*)(sm + bo + BL_O + bnn * 48 + 16) = l2v;
    };
    auto MMA = [&](uint32_t bo) {
        uint32_t ah[4], al[4];
        ldm4(ah, a_base + bo);
        ldm4(al, a_base + bo + AL_O);
        #pragma unroll
        for (int j = 0; j < 8; j++) {
            uint32_t bh[4], bl[4];
            ldm4(bh, b_base + bo + j * 768);
            ldm4(bl, b_base + bo + (BL_O - BH_O) + j * 768);
            mma16816(acc[2*j],   ah, bh[0], bh[2]);
            mma16816(acc[2*j],   ah, bl[0], bl[2]);
            mma16816(acc[2*j],   al, bh[0], bh[2]);
            mma16816(acc[2*j+1], ah, bh[1], bh[3]);
            mma16816(acc[2*j+1], ah, bl[1], bl[3]);
            mma16816(acc[2*j+1], al, bh[1], bh[3]);
        }
    };

    LOAD(0); CVSTS(0);
    __syncthreads();
    for (int ch = 0; ch < 16; ch++) {
        if (ch < 15) LOAD(ch + 1);
        MMA((ch & 1) * BUFSZ);
        if (ch < 15) CVSTS(((ch + 1) & 1) * BUFSZ);
        __syncthreads();
    }

    // ---------------- fused masked softmax over n ----------------
    const int l2 = lane & 3;
    const int rA = mw * 16 + (lane >> 2), rB = rA + 8;
    const int mA = m0 + rA, mB = mA + 8;
    const int mAc = (mA < MH) ? mA : MH - 1, mBc = (mB < MH) ? mB : MH - 1;
    const int xmA = mAc / 15, ymA = mAc - 15 * xmA;
    const int xmB = mBc / 15, ymB = mBc - 15 * xmB;

    float mxA = -1e30f, mxB = -1e30f;
    #pragma unroll
    for (int nt = 0; nt < 16; nt++) {
        #pragma unroll
        for (int c = 0; c < 2; c++) {
            int n = nh * 128 + nt * 8 + 2 * l2 + c;
            int xn = n / 15, yn = n - 15 * xn;
            bool ok = n < NC;
            float vA = ok ? acc[nt][c]     * PWS[iabs(xn - xmA) + iabs(yn - ymA)] : -1e30f;
            float vB = ok ? acc[nt][2 + c] * PWS[iabs(xn - xmB) + iabs(yn - ymB)] : -1e30f;
            acc[nt][c] = vA; acc[nt][2 + c] = vB;
            mxA = fmaxf(mxA, vA); mxB = fmaxf(mxB, vB);
        }
    }
    mxA = fmaxf(mxA, __shfl_xor_sync(~0u, mxA, 1)); mxA = fmaxf(mxA, __shfl_xor_sync(~0u, mxA, 2));
    mxB = fmaxf(mxB, __shfl_xor_sync(~0u, mxB, 1)); mxB = fmaxf(mxB, __shfl_xor_sync(~0u, mxB, 2));
    if (l2 == 0) { RMX[nh * 64 + rA] = mxA; RMX[nh * 64 + rB] = mxB; }
    __syncthreads();
    mxA = fmaxf(RMX[rA], RMX[64 + rA]);
    mxB = fmaxf(RMX[rB], RMX[64 + rB]);

    float sA = 0.f, sB = 0.f;
    #pragma unroll
    for (int nt = 0; nt < 16; nt++) {
        sA += __expf(acc[nt][0] - mxA) + __expf(acc[nt][1] - mxA);
        sB += __expf(acc[nt][2] - mxB) + __expf(acc[nt][3] - mxB);
    }
    sA += __shfl_xor_sync(~0u, sA, 1); sA += __shfl_xor_sync(~0u, sA, 2);
    sB += __shfl_xor_sync(~0u, sB, 1); sB += __shfl_xor_sync(~0u, sB, 2);
    if (l2 == 0) { RS[nh * 64 + rA] = sA; RS[nh * 64 + rB] = sB; }
    __syncthreads();
    const float invA = 1.0f / (RS[rA] + RS[64 + rA]);
    const float invB = 1.0f / (RS[rB] + RS[64 + rB]);

    uint32_t* ptha = g_pt_hi + ((size_t)b * 256 + mA) * 128;
    uint32_t* ptla = g_pt_lo + ((size_t)b * 256 + mA) * 128;
    uint32_t* pthb = g_pt_hi + ((size_t)b * 256 + mB) * 128;
    uint32_t* ptlb = g_pt_lo + ((size_t)b * 256 + mB) * 128;
    float* pbase = p_out + (size_t)b * NC * MH;

    #pragma unroll
    for (int nt = 0; nt < 16; nt++) {
        int n0 = nh * 128 + nt * 8 + 2 * l2;
        float pA0 = __expf(acc[nt][0] - mxA) * invA;
        float pA1 = __expf(acc[nt][1] - mxA) * invA;
        float pB0 = __expf(acc[nt][2] - mxB) * invB;
        float pB1 = __expf(acc[nt][3] - mxB) * invB;
        uint32_t loA, hiA = pack_hi2(pA0, pA1, loA);
        uint32_t loB, hiB = pack_hi2(pB0, pB1, loB);
        int wd = nh * 64 + nt * 4 + l2;
        ptha[wd] = hiA; ptla[wd] = loA;
        pthb[wd] = hiB; ptlb[wd] = loB;
        if (mA < MH) {
            if (n0 < NC)     pbase[(size_t)n0 * MH + mA] = pA0;
            if (n0 + 1 < NC) pbase[(size_t)(n0 + 1) * MH + mA] = pA1;
        }
        if (mB < MH) {
            if (n0 < NC)     pbase[(size_t)n0 * MH + mB] = pB0;
            if (n0 + 1 < NC) pbase[(size_t)(n0 + 1) * MH + mB] = pB1;
        }
    }
}

// =============================== GEMM2 =====================================
// Tile 64m x 256v. A = pt scratch (pre-split), B = m_out^T (in-kernel T).
__global__ __launch_bounds__(256, 2)
void k_g2(const float* __restrict__ m_out, float* __restrict__ out)
{
    extern __shared__ char sm[];
    const uint32_t su = smem_u32(sm);
    const int tid = threadIdx.x, lane = tid & 31, w = tid >> 5;
    const int mw = w & 3, nh = w >> 2;
    const int b = blockIdx.y, m0 = blockIdx.x * 64;

    const float* Bo = m_out + (size_t)b * NC * VD;   // [n][v]

    float acc[16][4];
    #pragma unroll
    for (int i = 0; i < 16; i++) { acc[i][0] = acc[i][1] = acc[i][2] = acc[i][3] = 0.f; }

    const int g = lane >> 3, rr = lane & 7;
    const uint32_t a_base = su + (uint32_t)((mw * 16 + (g & 1) * 8 + rr) * 48 + (g >> 1) * 16);
    const uint32_t b_base = su + BH_O + (uint32_t)((nh * 128 + (g & 1) * 8 + rr) * 48 + (g >> 1) * 16);

    const int amm = tid >> 2, aw = tid & 3;   // A: row m, 2 words
    const int bvv = tid;                      // B: one v row, 16 n's
    uint2 ha, la;
    float fb[16];

    auto LOAD = [&](int ch) {
        size_t gi = ((size_t)b * 256 + m0 + amm) * 128 + ch * 8 + aw * 2;
        ha = *(const uint2*)&g_pt_hi[gi];
        la = *(const uint2*)&g_pt_lo[gi];
        const int n0 = ch * 16;
        #pragma unroll
        for (int t = 0; t < 16; t++) {
            int n = n0 + t;
            fb[t] = (n < NC) ? Bo[(size_t)n * VD + bvv] : 0.0f;
        }
    };
    auto CVSTS = [&](int bo) {
        *(uint2*)(sm + bo + amm * 48 + aw * 8) = ha;
        *(uint2*)(sm + bo + AL_O + amm * 48 + aw * 8) = la;
        uint4 h1, l1, h2, l2v;
        h1.x = pack_hi2(fb[0], fb[1], l1.x);  h1.y = pack_hi2(fb[2], fb[3], l1.y);
        h1.z = pack_hi2(fb[4], fb[5], l1.z);  h1.w = pack_hi2(fb[6], fb[7], l1.w);
        h2.x = pack_hi2(fb[8], fb[9], l2v.x); h2.y = pack_hi2(fb[10], fb[11], l2v.y);
        h2.z = pack_hi2(fb[12], fb[13], l2v.z); h2.w = pack_hi2(fb[14], fb[15], l2v.w);
        *(uint4*)(sm + bo + BH_O + bvv * 48) = h1;
        *(uint4*)(sm + bo + BH_O + bvv * 48 + 16) = h2;
        *(uint4*)(sm + bo + BL_O + bvv * 48) = l1;
        *(uint4*)(sm + bo + BL_O + bvv * 48 + 16) = l2v;
    };
    auto MMA = [&](uint32_t bo) {
        uint32_t ah[4], al[4];
        ldm4(ah, a_base + bo);
        ldm4(al, a_base + bo + AL_O);
        #pragma unroll
        for (int j = 0; j < 8; j++) {
            uint32_t bh[4], bl[4];
            ldm4(bh, b_base + bo + j * 768);
            ldm4(bl, b_base + bo + (BL_O - BH_O) + j * 768);
            mma16816(acc[2*j],   ah, bh[0], bh[2]);
            mma16816(acc[2*j],   ah, bl[0], bl[2]);
            mma16816(acc[2*j],   al, bh[0], bh[2]);
            mma16816(acc[2*j+1], ah, bh[1], bh[3]);
            mma16816(acc[2*j+1], ah, bl[1], bl[3]);
            mma16816(acc[2*j+1], al, bh[1], bh[3]);
        }
    };

    LOAD(0); CVSTS(0);
    __syncthreads();
    for (int ch = 0; ch < 16; ch++) {
        if (ch < 15) LOAD(ch + 1);
        MMA((ch & 1) * BUFSZ);
        if (ch < 15) CVSTS(((ch + 1) & 1) * BUFSZ);
        __syncthreads();
    }

    const int l2 = lane & 3;
    const int mA = m0 + mw * 16 + (lane >> 2);
    const int mB = mA + 8;
    float* obase = out + (size_t)b * OUTC * MH;
    #pragma unroll
    for (int nt = 0; nt < 16; nt++) {
        int v0 = nh * 128 + nt * 8 + 2 * l2;
        if (mA < MH) {
            obase[(size_t)v0 * MH + mA]       = acc[nt][0];
            obase[(size_t)(v0 + 1) * MH + mA] = acc[nt][1];
        }
        if (mB < MH) {
            obase[(size_t)v0 * MH + mB]       = acc[nt][2];
            obase[(size_t)(v0 + 1) * MH + mB] = acc[nt][3];
        }
    }
}

// ============================ concat copy ==================================
__global__ __launch_bounds__(256) void k_copy(const float4* __restrict__ q,
                                              float* __restrict__ out)
{
    const int TOT4 = (B_ * 256 * MH) / 4;
    int i = blockIdx.x * blockDim.x + threadIdx.x;
    if (i >= TOT4) return;
    int b = i / 14400;
    float4 v = q[i];
    *(float4*)(out + (size_t)(b + 1) * 57600 + (size_t)i * 4) = v;
}

// ---------------------------------------------------------------------------
extern "C" void kernel_launch(void* const* d_in, const int* in_sizes, int n_in,
                              void* d_out, int out_size)
{
    const float* m_in  = (const float*)d_in[0];
    const float* m_out = (const float*)d_in[1];
    const float* q_in  = (const float*)d_in[2];
    const float* q_out = (const float*)d_in[3];
    float* out = (float*)d_out;
    float* p   = out + (size_t)B_ * OUTC * MH;

    static int inited = 0;
    if (!inited) {
        cudaFuncSetAttribute(k_g1, cudaFuncAttributeMaxDynamicSharedMemorySize, SM_G1);
        cudaFuncSetAttribute(k_g2, cudaFuncAttributeMaxDynamicSharedMemorySize, SM_G2);
        inited = 1;
    }

    k_g1<<<dim3(4, B_), 256, SM_G1>>>(q_in, m_in, p);
    k_g2<<<dim3(4, B_), 256, SM_G2>>>(m_out, out);
    const int TOT4 = (B_ * 256 * MH) / 4;
    k_copy<<<(TOT4 + 255) / 256, 256>>>((const float4*)q_out, out);
}

// round 7
// speedup vs baseline: 1.3368x; 1.3368x over previous
#include <cuda_runtime.h>
#include <cuda_bf16.h>
#include <cstdint>

#define B_   512
#define NC   225
#define CK   256
#define MH   225
#define VD   256
#define OUTC 512

// ---------------- helpers ----------------
__device__ __forceinline__ uint32_t smem_u32(const void* p) {
    uint32_t a;
    asm("{ .reg .u64 t; cvta.to.shared.u64 t, %1; cvt.u32.u64 %0, t; }" : "=r"(a) : "l"(p));
    return a;
}
__device__ __forceinline__ uint32_t cvt_tf32(float f) {
    uint32_t r;
    asm("cvt.rna.tf32.f32 %0, %1;" : "=r"(r) : "f"(f));
    return r;
}
__device__ __forceinline__ void ldm4(uint32_t* r, uint32_t addr) {
    asm volatile("ldmatrix.sync.aligned.m8n8.x4.shared.b16 {%0,%1,%2,%3}, [%4];"
                 : "=r"(r[0]), "=r"(r[1]), "=r"(r[2]), "=r"(r[3]) : "r"(addr));
}
__device__ __forceinline__ void mma1688(float* d, const uint32_t* a, uint32_t b0, uint32_t b1) {
    asm volatile("mma.sync.aligned.m16n8k8.row.col.f32.tf32.tf32.f32 "
                 "{%0,%1,%2,%3}, {%4,%5,%6,%7}, {%8,%9}, {%0,%1,%2,%3};"
                 : "+f"(d[0]), "+f"(d[1]), "+f"(d[2]), "+f"(d[3])
                 : "r"(a[0]), "r"(a[1]), "r"(a[2]), "r"(a[3]), "r"(b0), "r"(b1));
}
__device__ __forceinline__ int iabs(int x) { return x < 0 ? -x : x; }

// smem per buffer (K=16 chunk, f32, pitch 80B = 20 words; 20 mod 32 pattern is
// conflict-free for 8-row 16B phases): A 64x80=5120 | B 256x80=20480 => 25600
#define BUFB   5120
#define BUFSZ  25600
#define PW_O   51200             // 40 floats
#define RMX_O  51360             // 4*64 floats
#define RS_O   52384             // 4*64 floats
#define SM_G1  53408
#define SM_G2  51200

// =============================== GEMM1 =====================================
// D[m,n] = S^T (tf32), masked, softmax over n fused.
// CTA tile 64m x 256n; 8 warps: mw = w&1 (32m strip), nh = w>>1 (64n quarter).
__global__ __launch_bounds__(256, 2)
void k_g1(const float* __restrict__ q_in, const float* __restrict__ m_in,
          float* __restrict__ p_out)
{
    extern __shared__ char sm[];
    const uint32_t su = smem_u32(sm);
    const int tid = threadIdx.x, lane = tid & 31, w = tid >> 5;
    const int mw = w & 1, nh = w >> 1;
    const int b = blockIdx.y, m0 = blockIdx.x * 64;

    float* PWS = (float*)(sm + PW_O);
    float* RMX = (float*)(sm + RMX_O);
    float* RS  = (float*)(sm + RS_O);
    if (tid < 32) {
        float v = 0.0625f;               // fold 1/sqrt(256)
        for (int i = 0; i < tid; i++) v *= 0.92f;
        PWS[tid] = v;
    }

    const float* Aq = q_in + (size_t)b * CK * MH;   // [c][m]
    const float* Bm = m_in + (size_t)b * NC * CK;   // [n][c]

    float acc[2][8][4];
    #pragma unroll
    for (int s = 0; s < 2; s++)
        #pragma unroll
        for (int j = 0; j < 8; j++)
            #pragma unroll
            for (int c = 0; c < 4; c++) acc[s][j][c] = 0.f;

    // ldmatrix lane address components
    const int row_a = (lane & 7) + ((lane >> 3) & 1) * 8;
    const int koff_a = (lane >> 4) * 16;
    const int nloc_b = (lane & 7) + ((lane >> 4) & 1) * 8;
    const int koff_b = ((lane >> 3) & 1) * 16;
    uint32_t a_ad[2], b_ad[4];
    #pragma unroll
    for (int s = 0; s < 2; s++)
        a_ad[s] = su + (uint32_t)((mw * 32 + s * 16 + row_a) * 80 + koff_a);
    #pragma unroll
    for (int jp = 0; jp < 4; jp++)
        b_ad[jp] = su + BUFB + (uint32_t)((nh * 64 + jp * 16 + nloc_b) * 80 + koff_b);

    // staging maps
    const int amm = tid & 63, acb = (tid >> 6) * 4;  // A: row m, 4 c's
    const int agm = m0 + amm;
    const int bnn = tid;                             // B: one n row, 16 c's
    float fa[4], fb[16];

    auto LOAD = [&](int ch) {
        const int c0 = ch * 16;
        #pragma unroll
        for (int t = 0; t < 4; t++)
            fa[t] = (agm < MH) ? Aq[(size_t)(c0 + acb + t) * MH + agm] : 0.0f;
        if (bnn < NC) {
            const float* br = Bm + (size_t)bnn * CK + c0;
            #pragma unroll
            for (int t = 0; t < 4; t++) *(float4*)(fb + 4 * t) = *(const float4*)(br + 4 * t);
        } else {
            #pragma unroll
            for (int t = 0; t < 16; t++) fb[t] = 0.0f;
        }
    };
    auto CVSTS = [&](int bo) {
        uint4 av;
        av.x = cvt_tf32(fa[0]); av.y = cvt_tf32(fa[1]);
        av.z = cvt_tf32(fa[2]); av.w = cvt_tf32(fa[3]);
        *(uint4*)(sm + bo + amm * 80 + acb * 4) = av;
        #pragma unroll
        for (int q = 0; q < 4; q++) {
            uint4 bv;
            bv.x = cvt_tf32(fb[4*q+0]); bv.y = cvt_tf32(fb[4*q+1]);
            bv.z = cvt_tf32(fb[4*q+2]); bv.w = cvt_tf32(fb[4*q+3]);
            *(uint4*)(sm + bo + BUFB + bnn * 80 + q * 16) = bv;
        }
    };
    auto MMA = [&](uint32_t bo) {
        #pragma unroll
        for (int ks = 0; ks < 2; ks++) {
            uint32_t a0[4], a1[4];
            ldm4(a0, a_ad[0] + bo + ks * 32);
            ldm4(a1, a_ad[1] + bo + ks * 32);
            #pragma unroll
            for (int jp = 0; jp < 4; jp++) {
                uint32_t bf[4];
                ldm4(bf, b_ad[jp] + bo + ks * 32);
                mma1688(acc[0][2*jp],   a0, bf[0], bf[1]);
                mma1688(acc[0][2*jp+1], a0, bf[2], bf[3]);
                mma1688(acc[1][2*jp],   a1, bf[0], bf[1]);
                mma1688(acc[1][2*jp+1], a1, bf[2], bf[3]);
            }
        }
    };

    LOAD(0); CVSTS(0);
    __syncthreads();
    for (int ch = 0; ch < 16; ch++) {
        if (ch < 15) LOAD(ch + 1);
        MMA((ch & 1) * BUFSZ);
        if (ch < 15) CVSTS(((ch + 1) & 1) * BUFSZ);
        __syncthreads();
    }

    // ---------------- fused masked softmax over n ----------------
    const int l4 = lane & 3, lr = lane >> 2;
    // 4 m-rows per thread: (s, h) -> local row
    int rl[2][2], xm[2][2], ym[2][2];
    #pragma unroll
    for (int s = 0; s < 2; s++)
        #pragma unroll
        for (int h = 0; h < 2; h++) {
            rl[s][h] = mw * 32 + s * 16 + lr + h * 8;
            int gm = m0 + rl[s][h];
            int gmc = (gm < MH) ? gm : MH - 1;
            xm[s][h] = gmc / 15; ym[s][h] = gmc - 15 * xm[s][h];
        }

    float mx[2][2] = {{-1e30f, -1e30f}, {-1e30f, -1e30f}};
    #pragma unroll
    for (int s = 0; s < 2; s++)
        #pragma unroll
        for (int j = 0; j < 8; j++)
            #pragma unroll
            for (int h = 0; h < 2; h++)
                #pragma unroll
                for (int c = 0; c < 2; c++) {
                    int n = nh * 64 + j * 8 + 2 * l4 + c;
                    int xn = n / 15, yn = n - 15 * xn;
                    float v = (n < NC)
                        ? acc[s][j][2*h+c] * PWS[iabs(xn - xm[s][h]) + iabs(yn - ym[s][h])]
                        : -1e30f;
                    acc[s][j][2*h+c] = v;
                    mx[s][h] = fmaxf(mx[s][h], v);
                }
    #pragma unroll
    for (int s = 0; s < 2; s++)
        #pragma unroll
        for (int h = 0; h < 2; h++) {
            mx[s][h] = fmaxf(mx[s][h], __shfl_xor_sync(~0u, mx[s][h], 1));
            mx[s][h] = fmaxf(mx[s][h], __shfl_xor_sync(~0u, mx[s][h], 2));
            if (l4 == 0) RMX[nh * 64 + rl[s][h]] = mx[s][h];
        }
    __syncthreads();
    #pragma unroll
    for (int s = 0; s < 2; s++)
        #pragma unroll
        for (int h = 0; h < 2; h++) {
            float m1 = fmaxf(RMX[rl[s][h]], RMX[64 + rl[s][h]]);
            float m2 = fmaxf(RMX[128 + rl[s][h]], RMX[192 + rl[s][h]]);
            mx[s][h] = fmaxf(m1, m2);
        }
    float sum[2][2] = {{0.f, 0.f}, {0.f, 0.f}};
    #pragma unroll
    for (int s = 0; s < 2; s++)
        #pragma unroll
        for (int j = 0; j < 8; j++)
            #pragma unroll
            for (int h = 0; h < 2; h++) {
                sum[s][h] += __expf(acc[s][j][2*h]   - mx[s][h]);
                sum[s][h] += __expf(acc[s][j][2*h+1] - mx[s][h]);
            }
    __syncthreads();   // protect RMX/RS reuse ordering
    #pragma unroll
    for (int s = 0; s < 2; s++)
        #pragma unroll
        for (int h = 0; h < 2; h++) {
            sum[s][h] += __shfl_xor_sync(~0u, sum[s][h], 1);
            sum[s][h] += __shfl_xor_sync(~0u, sum[s][h], 2);
            if (l4 == 0) RS[nh * 64 + rl[s][h]] = sum[s][h];
        }
    __syncthreads();
    float inv[2][2];
    #pragma unroll
    for (int s = 0; s < 2; s++)
        #pragma unroll
        for (int h = 0; h < 2; h++)
            inv[s][h] = 1.0f / (RS[rl[s][h]] + RS[64 + rl[s][h]]
                              + RS[128 + rl[s][h]] + RS[192 + rl[s][h]]);

    float* pbase = p_out + (size_t)b * NC * MH;
    #pragma unroll
    for (int s = 0; s < 2; s++)
        #pragma unroll
        for (int h = 0; h < 2; h++) {
            int gm = m0 + rl[s][h];
            if (gm >= MH) continue;
            #pragma unroll
            for (int j = 0; j < 8; j++) {
                int n0 = nh * 64 + j * 8 + 2 * l4;
                float p0 = __expf(acc[s][j][2*h]   - mx[s][h]) * inv[s][h];
                float p1 = __expf(acc[s][j][2*h+1] - mx[s][h]) * inv[s][h];
                if (n0 < NC)     pbase[(size_t)n0 * MH + gm] = p0;
                if (n0 + 1 < NC) pbase[(size_t)(n0 + 1) * MH + gm] = p1;
            }
        }
}

// =============================== GEMM2 =====================================
// D[m,v] = mem^T = p^T * m_out (tf32). A = p^T (transposed in-kernel from the
// p output region), B = m_out^T. CTA tile 64m x 256v, K = n (15 chunks of 16).
__global__ __launch_bounds__(256, 2)
void k_g2(const float* __restrict__ m_out, const float* __restrict__ p_in,
          float* __restrict__ out)
{
    extern __shared__ char sm[];
    const uint32_t su = smem_u32(sm);
    const int tid = threadIdx.x, lane = tid & 31, w = tid >> 5;
    const int mw = w & 1, nh = w >> 1;
    const int b = blockIdx.y, m0 = blockIdx.x * 64;

    const float* Bo = m_out + (size_t)b * NC * VD;   // [n][v]
    const float* P  = p_in + (size_t)b * NC * MH;    // [n][m]

    float acc[2][8][4];
    #pragma unroll
    for (int s = 0; s < 2; s++)
        #pragma unroll
        for (int j = 0; j < 8; j++)
            #pragma unroll
            for (int c = 0; c < 4; c++) acc[s][j][c] = 0.f;

    const int row_a = (lane & 7) + ((lane >> 3) & 1) * 8;
    const int koff_a = (lane >> 4) * 16;
    const int nloc_b = (lane & 7) + ((lane >> 4) & 1) * 8;
    const int koff_b = ((lane >> 3) & 1) * 16;
    uint32_t a_ad[2], b_ad[4];
    #pragma unroll
    for (int s = 0; s < 2; s++)
        a_ad[s] = su + (uint32_t)((mw * 32 + s * 16 + row_a) * 80 + koff_a);
    #pragma unroll
    for (int jp = 0; jp < 4; jp++)
        b_ad[jp] = su + BUFB + (uint32_t)((nh * 64 + jp * 16 + nloc_b) * 80 + koff_b);

    const int amm = tid & 63, anb = (tid >> 6) * 4;  // A: row m, 4 n's
    const int agm = m0 + amm;
    const int bvv = tid;                             // B: one v row, 16 n's
    float fa[4], fb[16];

    auto LOAD = [&](int ch) {
        const int n0 = ch * 16;
        #pragma unroll
        for (int t = 0; t < 4; t++) {
            int n = n0 + anb + t;
            fa[t] = (n < NC && agm < MH) ? P[(size_t)n * MH + agm] : 0.0f;
        }
        #pragma unroll
        for (int t = 0; t < 16; t++) {
            int n = n0 + t;
            fb[t] = (n < NC) ? Bo[(size_t)n * VD + bvv] : 0.0f;
        }
    };
    auto CVSTS = [&](int bo) {
        uint4 av;
        av.x = cvt_tf32(fa[0]); av.y = cvt_tf32(fa[1]);
        av.z = cvt_tf32(fa[2]); av.w = cvt_tf32(fa[3]);
        *(uint4*)(sm + bo + amm * 80 + anb * 4) = av;
        #pragma unroll
        for (int q = 0; q < 4; q++) {
            uint4 bv;
            bv.x = cvt_tf32(fb[4*q+0]); bv.y = cvt_tf32(fb[4*q+1]);
            bv.z = cvt_tf32(fb[4*q+2]); bv.w = cvt_tf32(fb[4*q+3]);
            *(uint4*)(sm + bo + BUFB + bvv * 80 + q * 16) = bv;
        }
    };
    auto MMA = [&](uint32_t bo) {
        #pragma unroll
        for (int ks = 0; ks < 2; ks++) {
            uint32_t a0[4], a1[4];
            ldm4(a0, a_ad[0] + bo + ks * 32);
            ldm4(a1, a_ad[1] + bo + ks * 32);
            #pragma unroll
            for (int jp = 0; jp < 4; jp++) {
                uint32_t bf[4];
                ldm4(bf, b_ad[jp] + bo + ks * 32);
                mma1688(acc[0][2*jp],   a0, bf[0], bf[1]);
                mma1688(acc[0][2*jp+1], a0, bf[2], bf[3]);
                mma1688(acc[1][2*jp],   a1, bf[0], bf[1]);
                mma1688(acc[1][2*jp+1], a1, bf[2], bf[3]);
            }
        }
    };

    LOAD(0); CVSTS(0);
    __syncthreads();
    for (int ch = 0; ch < 15; ch++) {      // 15*16 = 240 >= 225
        if (ch < 14) LOAD(ch + 1);
        MMA((ch & 1) * BUFSZ);
        if (ch < 14) CVSTS(((ch + 1) & 1) * BUFSZ);
        __syncthreads();
    }

    const int l4 = lane & 3, lr = lane >> 2;
    float* obase = out + (size_t)b * OUTC * MH;
    #pragma unroll
    for (int s = 0; s < 2; s++)
        #pragma unroll
        for (int h = 0; h < 2; h++) {
            int gm = m0 + mw * 32 + s * 16 + lr + h * 8;
            if (gm >= MH) continue;
            #pragma unroll
            for (int j = 0; j < 8; j++) {
                int v0 = nh * 64 + j * 8 + 2 * l4;
                obase[(size_t)v0 * MH + gm]       = acc[s][j][2*h];
                obase[(size_t)(v0 + 1) * MH + gm] = acc[s][j][2*h+1];
            }
        }
}

// ============================ concat copy ==================================
__global__ __launch_bounds__(256) void k_copy(const float4* __restrict__ q,
                                              float* __restrict__ out)
{
    const int TOT4 = (B_ * 256 * MH) / 4;
    int i = blockIdx.x * blockDim.x + threadIdx.x;
    if (i >= TOT4) return;
    int b = i / 14400;
    float4 v = q[i];
    *(float4*)(out + (size_t)(b + 1) * 57600 + (size_t)i * 4) = v;
}

// ---------------------------------------------------------------------------
extern "C" void kernel_launch(void* const* d_in, const int* in_sizes, int n_in,
                              void* d_out, int out_size)
{
    const float* m_in  = (const float*)d_in[0];
    const float* m_out = (const float*)d_in[1];
    const float* q_in  = (const float*)d_in[2];
    const float* q_out = (const float*)d_in[3];
    float* out = (float*)d_out;
    float* p   = out + (size_t)B_ * OUTC * MH;

    cudaFuncSetAttribute(k_g1, cudaFuncAttributeMaxDynamicSharedMemorySize, SM_G1);
    cudaFuncSetAttribute(k_g2, cudaFuncAttributeMaxDynamicSharedMemorySize, SM_G2);

    k_g1<<<dim3(4, B_), 256, SM_G1>>>(q_in, m_in, p);
    k_g2<<<dim3(4, B_), 256, SM_G2>>>(m_out, p, out);
    const int TOT4 = (B_ * 256 * MH) / 4;
    k_copy<<<(TOT4 + 255) / 256, 256>>>((const float4*)q_out, out);
}